// round 1
// baseline (speedup 1.0000x reference)
#include <cuda_runtime.h>
#include <math.h>

#define B_DIM   4096
#define ZDIM    128
#define IN_DIM  512
#define H_DIM   1024
#define SEQ_LEN 12

#define BM 128
#define BN 128
#define BK 16
#define PAD 4

// Scratch (allocation-free rule: __device__ globals)
__device__ float g_x0[B_DIM * IN_DIM];     // 8 MB
__device__ float g_state[B_DIM * H_DIM];   // 16 MB
__device__ float g_spre[B_DIM * H_DIM];    // 16 MB
__device__ float g_u[B_DIM * H_DIM];       // 16 MB
__device__ float g_rs[B_DIM * H_DIM];      // 16 MB

enum { EPI_LIN = 0, EPI_BELTA = 1, EPI_SIGU = 2, EPI_SIGR = 3, EPI_NEW = 4 };

__global__ void zero_kernel(float* __restrict__ p, int n) {
    int i = blockIdx.x * blockDim.x + threadIdx.x;
    if (i < n) p[i] = 0.0f;
}

__device__ __forceinline__ float4 ldA(const float* __restrict__ A1, int lda1, int K1,
                                      const float* __restrict__ A2, int lda2,
                                      int m, int k) {
    // Tile never straddles K1 boundary (BK divides K1), so branch is warp-uniform.
    if (k < K1) return *(const float4*)(A1 + (size_t)m * lda1 + k);
    return *(const float4*)(A2 + (size_t)m * lda2 + (k - K1));
}

// C[M,N] = epi( [A1 | A2] @ W + bias ),  W is (K1+K2, N) row-major.
template <int EPI>
__global__ __launch_bounds__(256, 2)
void gemm_epi(const float* __restrict__ A1, int lda1, int K1,
              const float* __restrict__ A2, int lda2, int K2,
              const float* __restrict__ W,
              const float* __restrict__ bias,
              const float* __restrict__ ex1,   // BELTA: state | SIGR: spre | NEW: u
              const float* __restrict__ ex2,   // NEW: spre
              float* __restrict__ C, int ldc, int N)
{
    __shared__ float As[2][BK][BM + PAD];
    __shared__ float Bs[2][BK][BN];

    const int tid = threadIdx.x;
    const int tx = tid & 15;          // 0..15 -> 8 cols each
    const int ty = tid >> 4;          // 0..15 -> 8 rows each
    const int bm = blockIdx.y * BM;
    const int bn = blockIdx.x * BN;

    const int KT = (K1 + K2) / BK;

    // A-tile loader mapping: 2 float4 per thread
    const int ar0 = tid >> 2;                  // 0..63
    const int ac0 = (tid & 3) * 4;             // 0,4,8,12
    // B-tile loader mapping: 2 float4 per thread
    const int br0 = tid >> 5;                  // 0..7
    const int bc0 = (tid & 31) * 4;            // 0..124

    float acc[8][8];
#pragma unroll
    for (int i = 0; i < 8; i++)
#pragma unroll
        for (int j = 0; j < 8; j++) acc[i][j] = 0.0f;

    // ---- prologue: load tile 0 into buffer 0 ----
    {
        float4 a0 = ldA(A1, lda1, K1, A2, lda2, bm + ar0,      ac0);
        float4 a1 = ldA(A1, lda1, K1, A2, lda2, bm + ar0 + 64, ac0);
        float4 b0 = *(const float4*)(W + (size_t)(br0)*N + bn + bc0);
        float4 b1 = *(const float4*)(W + (size_t)(br0 + 8) * N + bn + bc0);
        As[0][ac0 + 0][ar0] = a0.x; As[0][ac0 + 1][ar0] = a0.y;
        As[0][ac0 + 2][ar0] = a0.z; As[0][ac0 + 3][ar0] = a0.w;
        As[0][ac0 + 0][ar0 + 64] = a1.x; As[0][ac0 + 1][ar0 + 64] = a1.y;
        As[0][ac0 + 2][ar0 + 64] = a1.z; As[0][ac0 + 3][ar0 + 64] = a1.w;
        *(float4*)&Bs[0][br0][bc0]     = b0;
        *(float4*)&Bs[0][br0 + 8][bc0] = b1;
    }
    __syncthreads();

    for (int kt = 0; kt < KT; kt++) {
        const int buf = kt & 1;
        float4 a0n, a1n, b0n, b1n;
        const bool more = (kt + 1 < KT);
        if (more) {
            const int ks = (kt + 1) * BK;
            a0n = ldA(A1, lda1, K1, A2, lda2, bm + ar0,      ks + ac0);
            a1n = ldA(A1, lda1, K1, A2, lda2, bm + ar0 + 64, ks + ac0);
            b0n = *(const float4*)(W + (size_t)(ks + br0) * N + bn + bc0);
            b1n = *(const float4*)(W + (size_t)(ks + br0 + 8) * N + bn + bc0);
        }

#pragma unroll
        for (int k = 0; k < BK; k++) {
            float a[8], b[8];
            *(float4*)&a[0] = *(const float4*)&As[buf][k][ty * 8];
            *(float4*)&a[4] = *(const float4*)&As[buf][k][ty * 8 + 4];
            *(float4*)&b[0] = *(const float4*)&Bs[buf][k][tx * 8];
            *(float4*)&b[4] = *(const float4*)&Bs[buf][k][tx * 8 + 4];
#pragma unroll
            for (int i = 0; i < 8; i++)
#pragma unroll
                for (int j = 0; j < 8; j++)
                    acc[i][j] = fmaf(a[i], b[j], acc[i][j]);
        }

        if (more) {
            const int nb = buf ^ 1;
            As[nb][ac0 + 0][ar0] = a0n.x; As[nb][ac0 + 1][ar0] = a0n.y;
            As[nb][ac0 + 2][ar0] = a0n.z; As[nb][ac0 + 3][ar0] = a0n.w;
            As[nb][ac0 + 0][ar0 + 64] = a1n.x; As[nb][ac0 + 1][ar0 + 64] = a1n.y;
            As[nb][ac0 + 2][ar0 + 64] = a1n.z; As[nb][ac0 + 3][ar0 + 64] = a1n.w;
            *(float4*)&Bs[nb][br0][bc0]     = b0n;
            *(float4*)&Bs[nb][br0 + 8][bc0] = b1n;
        }
        __syncthreads();
    }

    // ---- epilogue ----
#pragma unroll
    for (int i = 0; i < 8; i++) {
        const int m = bm + ty * 8 + i;
#pragma unroll
        for (int j = 0; j < 8; j++) {
            const int n = bn + tx * 8 + j;
            float v = acc[i][j] + bias[n];
            const size_t co = (size_t)m * ldc + n;
            const size_t eo = (size_t)m * H_DIM + n;
            if (EPI == EPI_LIN) {
                C[co] = v;
            } else if (EPI == EPI_BELTA) {
                float bl = __expf(-fmaxf(v, 0.0f));
                C[co] = bl * ex1[eo];                       // spre = belta * state
            } else if (EPI == EPI_SIGU) {
                C[co] = 1.0f / (1.0f + __expf(-v));         // u
            } else if (EPI == EPI_SIGR) {
                float r = 1.0f / (1.0f + __expf(-v));
                C[co] = r * ex1[eo];                        // r * spre
            } else if (EPI == EPI_NEW) {
                float ns = tanhf(v);
                float u = ex1[eo];
                float sp = ex2[eo];
                C[co] = (1.0f - u) * sp + u * ns;           // new state
            }
        }
    }
}

extern "C" void kernel_launch(void* const* d_in, const int* in_sizes, int n_in,
                              void* d_out, int out_size)
{
    const float* z       = (const float*)d_in[0];
    const float* td      = (const float*)d_in[1];
    const float* W_belta = (const float*)d_in[2];
    const float* b_belta = (const float*)d_in[3];
    const float* W_z     = (const float*)d_in[4];
    const float* b_z     = (const float*)d_in[5];
    const float* W1      = (const float*)d_in[6];
    const float* b1      = (const float*)d_in[7];
    const float* W2      = (const float*)d_in[8];
    const float* b2      = (const float*)d_in[9];
    const float* W3      = (const float*)d_in[10];
    const float* b3      = (const float*)d_in[11];
    const float* W_out   = (const float*)d_in[12];
    const float* b_out   = (const float*)d_in[13];
    float* out = (float*)d_out;

    float *x0, *st, *sp, *u, *rs;
    cudaGetSymbolAddress((void**)&x0, g_x0);
    cudaGetSymbolAddress((void**)&st, g_state);
    cudaGetSymbolAddress((void**)&sp, g_spre);
    cudaGetSymbolAddress((void**)&u,  g_u);
    cudaGetSymbolAddress((void**)&rs, g_rs);

    // state must start at zero on EVERY launch (graph replay determinism)
    zero_kernel<<<(B_DIM * H_DIM + 1023) / 1024, 1024>>>(st, B_DIM * H_DIM);

    const dim3 blk(256);
    const dim3 gridH(H_DIM / BN, B_DIM / BM);   // (8, 32)
    const dim3 gridI(IN_DIM / BN, B_DIM / BM);  // (4, 32)
    const int ldo = SEQ_LEN * IN_DIM;

    // x0 = z @ W_z + b_z
    gemm_epi<EPI_LIN><<<gridI, blk>>>(z, ZDIM, ZDIM, nullptr, 0, 0,
                                      W_z, b_z, nullptr, nullptr,
                                      x0, IN_DIM, IN_DIM);

    for (int t = 0; t < SEQ_LEN; t++) {
        const float* xp = (t == 0) ? x0 : out + (size_t)(t - 1) * IN_DIM;
        const int ldx   = (t == 0) ? IN_DIM : ldo;

        // spre = exp(-relu(td_t @ W_belta + b)) * state
        gemm_epi<EPI_BELTA><<<gridH, blk>>>(td + (size_t)t * IN_DIM, ldo, IN_DIM,
                                            nullptr, 0, 0,
                                            W_belta, b_belta, st, nullptr,
                                            sp, H_DIM, H_DIM);
        // u = sigmoid([spre|x] @ W1 + b1)
        gemm_epi<EPI_SIGU><<<gridH, blk>>>(sp, H_DIM, H_DIM, xp, ldx, IN_DIM,
                                           W1, b1, nullptr, nullptr,
                                           u, H_DIM, H_DIM);
        // rs = sigmoid([spre|x] @ W2 + b2) * spre
        gemm_epi<EPI_SIGR><<<gridH, blk>>>(sp, H_DIM, H_DIM, xp, ldx, IN_DIM,
                                           W2, b2, sp, nullptr,
                                           rs, H_DIM, H_DIM);
        // state = (1-u)*spre + u*tanh([rs|x] @ W3 + b3)
        gemm_epi<EPI_NEW><<<gridH, blk>>>(rs, H_DIM, H_DIM, xp, ldx, IN_DIM,
                                          W3, b3, u, sp,
                                          st, H_DIM, H_DIM);
        // out_t = state @ W_out + b_out   (written strided into d_out[:, t, :])
        gemm_epi<EPI_LIN><<<gridI, blk>>>(st, H_DIM, H_DIM, nullptr, 0, 0,
                                          W_out, b_out, nullptr, nullptr,
                                          out + (size_t)t * IN_DIM, ldo, IN_DIM);
    }
}

// round 2
// speedup vs baseline: 1.0014x; 1.0014x over previous
#include <cuda_runtime.h>
#include <math.h>

#define B_DIM   4096
#define ZDIM    128
#define IN_DIM  512
#define H_DIM   1024
#define SEQ_LEN 12

#define BM 128
#define BN 128
#define BK 16
#define PAD 4

// Scratch (allocation-free rule: __device__ globals)
__device__ float g_x0[B_DIM * IN_DIM];     // 8 MB
__device__ float g_state[B_DIM * H_DIM];   // 16 MB
__device__ float g_spre[B_DIM * H_DIM];    // 16 MB
__device__ float g_u[B_DIM * H_DIM];       // 16 MB
__device__ float g_rs[B_DIM * H_DIM];      // 16 MB

enum { EPI_LIN = 0, EPI_BELTA = 1, EPI_SIGU = 2, EPI_SIGR = 3, EPI_NEW = 4 };

__global__ void zero_kernel(float* __restrict__ p, int n) {
    int i = blockIdx.x * blockDim.x + threadIdx.x;
    if (i < n) p[i] = 0.0f;
}

__device__ __forceinline__ float4 ldA(const float* __restrict__ A1, int lda1, int K1,
                                      const float* __restrict__ A2, int lda2,
                                      int m, int k) {
    // Tile never straddles K1 boundary (BK divides K1), so branch is warp-uniform.
    if (k < K1) return *(const float4*)(A1 + (size_t)m * lda1 + k);
    return *(const float4*)(A2 + (size_t)m * lda2 + (k - K1));
}

// C[M,N] = epi( [A1 | A2] @ W + bias ),  W is (K1+K2, N) row-major.
template <int EPI>
__global__ __launch_bounds__(256, 2)
void gemm_epi(const float* __restrict__ A1, int lda1, int K1,
              const float* __restrict__ A2, int lda2, int K2,
              const float* __restrict__ W,
              const float* __restrict__ bias,
              const float* __restrict__ ex1,   // BELTA: state | SIGR: spre | NEW: u
              const float* __restrict__ ex2,   // NEW: spre
              float* __restrict__ C, int ldc, int N)
{
    __shared__ float As[2][BK][BM + PAD];
    __shared__ float Bs[2][BK][BN];

    const int tid = threadIdx.x;
    const int tx = tid & 15;          // 0..15 -> 8 cols each
    const int ty = tid >> 4;          // 0..15 -> 8 rows each
    const int bm = blockIdx.y * BM;
    const int bn = blockIdx.x * BN;

    const int KT = (K1 + K2) / BK;

    // A-tile loader mapping: 2 float4 per thread
    const int ar0 = tid >> 2;                  // 0..63
    const int ac0 = (tid & 3) * 4;             // 0,4,8,12
    // B-tile loader mapping: 2 float4 per thread
    const int br0 = tid >> 5;                  // 0..7
    const int bc0 = (tid & 31) * 4;            // 0..124

    float acc[8][8];
#pragma unroll
    for (int i = 0; i < 8; i++)
#pragma unroll
        for (int j = 0; j < 8; j++) acc[i][j] = 0.0f;

    // ---- prologue: load tile 0 into buffer 0 ----
    {
        float4 a0 = ldA(A1, lda1, K1, A2, lda2, bm + ar0,      ac0);
        float4 a1 = ldA(A1, lda1, K1, A2, lda2, bm + ar0 + 64, ac0);
        float4 b0 = *(const float4*)(W + (size_t)(br0)*N + bn + bc0);
        float4 b1 = *(const float4*)(W + (size_t)(br0 + 8) * N + bn + bc0);
        As[0][ac0 + 0][ar0] = a0.x; As[0][ac0 + 1][ar0] = a0.y;
        As[0][ac0 + 2][ar0] = a0.z; As[0][ac0 + 3][ar0] = a0.w;
        As[0][ac0 + 0][ar0 + 64] = a1.x; As[0][ac0 + 1][ar0 + 64] = a1.y;
        As[0][ac0 + 2][ar0 + 64] = a1.z; As[0][ac0 + 3][ar0 + 64] = a1.w;
        *(float4*)&Bs[0][br0][bc0]     = b0;
        *(float4*)&Bs[0][br0 + 8][bc0] = b1;
    }
    __syncthreads();

    for (int kt = 0; kt < KT; kt++) {
        const int buf = kt & 1;
        float4 a0n, a1n, b0n, b1n;
        const bool more = (kt + 1 < KT);
        if (more) {
            const int ks = (kt + 1) * BK;
            a0n = ldA(A1, lda1, K1, A2, lda2, bm + ar0,      ks + ac0);
            a1n = ldA(A1, lda1, K1, A2, lda2, bm + ar0 + 64, ks + ac0);
            b0n = *(const float4*)(W + (size_t)(ks + br0) * N + bn + bc0);
            b1n = *(const float4*)(W + (size_t)(ks + br0 + 8) * N + bn + bc0);
        }

#pragma unroll
        for (int k = 0; k < BK; k++) {
            float a[8], b[8];
            *(float4*)&a[0] = *(const float4*)&As[buf][k][ty * 8];
            *(float4*)&a[4] = *(const float4*)&As[buf][k][ty * 8 + 4];
            *(float4*)&b[0] = *(const float4*)&Bs[buf][k][tx * 8];
            *(float4*)&b[4] = *(const float4*)&Bs[buf][k][tx * 8 + 4];
#pragma unroll
            for (int i = 0; i < 8; i++)
#pragma unroll
                for (int j = 0; j < 8; j++)
                    acc[i][j] = fmaf(a[i], b[j], acc[i][j]);
        }

        if (more) {
            const int nb = buf ^ 1;
            As[nb][ac0 + 0][ar0] = a0n.x; As[nb][ac0 + 1][ar0] = a0n.y;
            As[nb][ac0 + 2][ar0] = a0n.z; As[nb][ac0 + 3][ar0] = a0n.w;
            As[nb][ac0 + 0][ar0 + 64] = a1n.x; As[nb][ac0 + 1][ar0 + 64] = a1n.y;
            As[nb][ac0 + 2][ar0 + 64] = a1n.z; As[nb][ac0 + 3][ar0 + 64] = a1n.w;
            *(float4*)&Bs[nb][br0][bc0]     = b0n;
            *(float4*)&Bs[nb][br0 + 8][bc0] = b1n;
        }
        __syncthreads();
    }

    // ---- epilogue ----
#pragma unroll
    for (int i = 0; i < 8; i++) {
        const int m = bm + ty * 8 + i;
#pragma unroll
        for (int j = 0; j < 8; j++) {
            const int n = bn + tx * 8 + j;
            float v = acc[i][j] + bias[n];
            const size_t co = (size_t)m * ldc + n;
            const size_t eo = (size_t)m * H_DIM + n;
            if (EPI == EPI_LIN) {
                C[co] = v;
            } else if (EPI == EPI_BELTA) {
                float bl = __expf(-fmaxf(v, 0.0f));
                C[co] = bl * ex1[eo];                       // spre = belta * state
            } else if (EPI == EPI_SIGU) {
                C[co] = 1.0f / (1.0f + __expf(-v));         // u
            } else if (EPI == EPI_SIGR) {
                float r = 1.0f / (1.0f + __expf(-v));
                C[co] = r * ex1[eo];                        // r * spre
            } else if (EPI == EPI_NEW) {
                float ns = tanhf(v);
                float u = ex1[eo];
                float sp = ex2[eo];
                C[co] = (1.0f - u) * sp + u * ns;           // new state
            }
        }
    }
}

extern "C" void kernel_launch(void* const* d_in, const int* in_sizes, int n_in,
                              void* d_out, int out_size)
{
    const float* z       = (const float*)d_in[0];
    const float* td      = (const float*)d_in[1];
    const float* W_belta = (const float*)d_in[2];
    const float* b_belta = (const float*)d_in[3];
    const float* W_z     = (const float*)d_in[4];
    const float* b_z     = (const float*)d_in[5];
    const float* W1      = (const float*)d_in[6];
    const float* b1      = (const float*)d_in[7];
    const float* W2      = (const float*)d_in[8];
    const float* b2      = (const float*)d_in[9];
    const float* W3      = (const float*)d_in[10];
    const float* b3      = (const float*)d_in[11];
    const float* W_out   = (const float*)d_in[12];
    const float* b_out   = (const float*)d_in[13];
    float* out = (float*)d_out;

    float *x0, *st, *sp, *u, *rs;
    cudaGetSymbolAddress((void**)&x0, g_x0);
    cudaGetSymbolAddress((void**)&st, g_state);
    cudaGetSymbolAddress((void**)&sp, g_spre);
    cudaGetSymbolAddress((void**)&u,  g_u);
    cudaGetSymbolAddress((void**)&rs, g_rs);

    // state must start at zero on EVERY launch (graph replay determinism)
    zero_kernel<<<(B_DIM * H_DIM + 1023) / 1024, 1024>>>(st, B_DIM * H_DIM);

    const dim3 blk(256);
    const dim3 gridH(H_DIM / BN, B_DIM / BM);   // (8, 32)
    const dim3 gridI(IN_DIM / BN, B_DIM / BM);  // (4, 32)
    const int ldo = SEQ_LEN * IN_DIM;

    // x0 = z @ W_z + b_z
    gemm_epi<EPI_LIN><<<gridI, blk>>>(z, ZDIM, ZDIM, nullptr, 0, 0,
                                      W_z, b_z, nullptr, nullptr,
                                      x0, IN_DIM, IN_DIM);

    for (int t = 0; t < SEQ_LEN; t++) {
        const float* xp = (t == 0) ? x0 : out + (size_t)(t - 1) * IN_DIM;
        const int ldx   = (t == 0) ? IN_DIM : ldo;

        // spre = exp(-relu(td_t @ W_belta + b)) * state
        gemm_epi<EPI_BELTA><<<gridH, blk>>>(td + (size_t)t * IN_DIM, ldo, IN_DIM,
                                            nullptr, 0, 0,
                                            W_belta, b_belta, st, nullptr,
                                            sp, H_DIM, H_DIM);
        // u = sigmoid([spre|x] @ W1 + b1)
        gemm_epi<EPI_SIGU><<<gridH, blk>>>(sp, H_DIM, H_DIM, xp, ldx, IN_DIM,
                                           W1, b1, nullptr, nullptr,
                                           u, H_DIM, H_DIM);
        // rs = sigmoid([spre|x] @ W2 + b2) * spre
        gemm_epi<EPI_SIGR><<<gridH, blk>>>(sp, H_DIM, H_DIM, xp, ldx, IN_DIM,
                                           W2, b2, sp, nullptr,
                                           rs, H_DIM, H_DIM);
        // state = (1-u)*spre + u*tanh([rs|x] @ W3 + b3)
        gemm_epi<EPI_NEW><<<gridH, blk>>>(rs, H_DIM, H_DIM, xp, ldx, IN_DIM,
                                          W3, b3, u, sp,
                                          st, H_DIM, H_DIM);
        // out_t = state @ W_out + b_out   (written strided into d_out[:, t, :])
        gemm_epi<EPI_LIN><<<gridI, blk>>>(st, H_DIM, H_DIM, nullptr, 0, 0,
                                          W_out, b_out, nullptr, nullptr,
                                          out + (size_t)t * IN_DIM, ldo, IN_DIM);
    }
}